// round 8
// baseline (speedup 1.0000x reference)
#include <cuda_runtime.h>
#include <cuda_bf16.h>
#include <math.h>
#include <stdint.h>

// Problem dims (fixed)
#define T_DIM   32
#define N_BATCH 256
#define D_DIM   512
#define H_DIM   2048
#define M_ROWS  (T_DIM * N_BATCH)   // 8192
#define EPS_BN  1e-5f

// ---------------- scratch (device globals; no allocs allowed) ----------------
__device__ float g_h[(size_t)M_ROWS * H_DIM];   // fc1 pre-activation  (64 MB)
__device__ float g_s[(size_t)M_ROWS * H_DIM];   // layer-1 spikes      (64 MB)
__device__ float g_o[(size_t)M_ROWS * D_DIM];   // fc2 pre-activation  (16 MB)
__device__ float g_psum[8 * H_DIM];
__device__ float g_psq [8 * H_DIM];
__device__ float g_scale[H_DIM];
__device__ float g_shift[H_DIM];

// packed f32x2 FMA: per-lane rn semantics, identical rounding to scalar FFMA
__device__ __forceinline__ void fma2(unsigned long long& d,
                                     unsigned long long a, unsigned long long b) {
    asm("fma.rn.f32x2 %0, %1, %2, %0;" : "+l"(d) : "l"(a), "l"(b));
}
union U64F2 { unsigned long long u; float2 f; };

// ---------------- SGEMM: C[m,n] = bias[n] + sum_k A[m,k]*B[n,k] --------------
// A: [M x K] row-major, B: [N x K] row-major (K-contiguous), C: [M x N].
// 128x128 tile, BK=16, 256 threads, 8x8 per thread. Inner product uses packed
// fma.rn.f32x2 over row-pairs; B tile stored DUPLICATED in smem so broadcast
// pairs (b_j, b_j) come straight from LDS (no pack instructions).
// Per-output accumulation order is identical to the scalar version (bitwise).
__global__ __launch_bounds__(256)
void sgemm_nt_bias(const float* __restrict__ A, const float* __restrict__ B,
                   const float* __restrict__ bias, float* __restrict__ C,
                   int N, int K)
{
    __shared__ __align__(16) float As[2][16][128];
    __shared__ __align__(16) float Bs[2][16][256];   // value j duplicated at 2j, 2j+1

    const int tid = threadIdx.x;
    const int m0  = blockIdx.y * 128;
    const int n0  = blockIdx.x * 128;
    const int tm  = (tid >> 4) * 8;     // 0..120
    const int tn  = (tid & 15) * 8;     // 0..120

    const int lrow = tid >> 2;          // 0..63
    const int lk4  = (tid & 3) * 4;     // 0,4,8,12

    const float* Aptr = A + (size_t)(m0 + lrow) * K + lk4;
    const float* Bptr = B + (size_t)(n0 + lrow) * K + lk4;
    const size_t rstep = (size_t)64 * K;

    unsigned long long acc2[4][8];      // [row-pair][col], lo=row 2ip, hi=row 2ip+1
    #pragma unroll
    for (int i = 0; i < 4; i++)
        #pragma unroll
        for (int j = 0; j < 8; j++) acc2[i][j] = 0ULL;

    float4 ar0, ar1, br0, br1;

    // prologue: load k-tile 0 into smem buffer 0
    ar0 = *(const float4*)(Aptr);
    ar1 = *(const float4*)(Aptr + rstep);
    br0 = *(const float4*)(Bptr);
    br1 = *(const float4*)(Bptr + rstep);
    #pragma unroll
    for (int j = 0; j < 4; j++) {
        As[0][lk4 + j][lrow]      = ((const float*)&ar0)[j];
        As[0][lk4 + j][lrow + 64] = ((const float*)&ar1)[j];
        Bs[0][lk4 + j][2 * lrow]       = ((const float*)&br0)[j];
        Bs[0][lk4 + j][2 * lrow + 1]   = ((const float*)&br0)[j];
        Bs[0][lk4 + j][2 * lrow + 128] = ((const float*)&br1)[j];
        Bs[0][lk4 + j][2 * lrow + 129] = ((const float*)&br1)[j];
    }
    __syncthreads();

    const int nk = K >> 4;
    for (int kt = 0; kt < nk; kt++) {
        const int b = kt & 1;
        if (kt + 1 < nk) {
            const float* Ap = Aptr + (size_t)(kt + 1) * 16;
            const float* Bp = Bptr + (size_t)(kt + 1) * 16;
            ar0 = *(const float4*)(Ap);
            ar1 = *(const float4*)(Ap + rstep);
            br0 = *(const float4*)(Bp);
            br1 = *(const float4*)(Bp + rstep);
        }
        #pragma unroll
        for (int k = 0; k < 16; k++) {
            // A row-pairs: 4 packed (a_{tm+2ip}, a_{tm+2ip+1})
            ulonglong2 av0 = *(const ulonglong2*)&As[b][k][tm];
            ulonglong2 av1 = *(const ulonglong2*)&As[b][k][tm + 4];
            unsigned long long ap[4] = {av0.x, av0.y, av1.x, av1.y};
            // B broadcast pairs: 8 packed (b_j, b_j) from duplicated smem
            ulonglong2 bv0 = *(const ulonglong2*)&Bs[b][k][2 * tn];
            ulonglong2 bv1 = *(const ulonglong2*)&Bs[b][k][2 * tn + 4];
            ulonglong2 bv2 = *(const ulonglong2*)&Bs[b][k][2 * tn + 8];
            ulonglong2 bv3 = *(const ulonglong2*)&Bs[b][k][2 * tn + 12];
            unsigned long long bp[8] = {bv0.x, bv0.y, bv1.x, bv1.y,
                                        bv2.x, bv2.y, bv3.x, bv3.y};
            #pragma unroll
            for (int ip = 0; ip < 4; ip++)
                #pragma unroll
                for (int j = 0; j < 8; j++)
                    fma2(acc2[ip][j], ap[ip], bp[j]);
        }
        if (kt + 1 < nk) {
            const int nb = b ^ 1;
            #pragma unroll
            for (int j = 0; j < 4; j++) {
                As[nb][lk4 + j][lrow]      = ((const float*)&ar0)[j];
                As[nb][lk4 + j][lrow + 64] = ((const float*)&ar1)[j];
                Bs[nb][lk4 + j][2 * lrow]       = ((const float*)&br0)[j];
                Bs[nb][lk4 + j][2 * lrow + 1]   = ((const float*)&br0)[j];
                Bs[nb][lk4 + j][2 * lrow + 128] = ((const float*)&br1)[j];
                Bs[nb][lk4 + j][2 * lrow + 129] = ((const float*)&br1)[j];
            }
            __syncthreads();
        }
    }

    // epilogue: add bias, store (same math/order as scalar version)
    const float4 bb0 = *(const float4*)(bias + n0 + tn);
    const float4 bb1 = *(const float4*)(bias + n0 + tn + 4);
    #pragma unroll
    for (int ip = 0; ip < 4; ip++) {
        #pragma unroll
        for (int h = 0; h < 2; h++) {
            float row_acc[8];
            #pragma unroll
            for (int j = 0; j < 8; j++) {
                U64F2 u; u.u = acc2[ip][j];
                row_acc[j] = h ? u.f.y : u.f.x;
            }
            float4 c0, c1;
            c0.x = row_acc[0] + bb0.x;  c0.y = row_acc[1] + bb0.y;
            c0.z = row_acc[2] + bb0.z;  c0.w = row_acc[3] + bb0.w;
            c1.x = row_acc[4] + bb1.x;  c1.y = row_acc[5] + bb1.y;
            c1.z = row_acc[6] + bb1.z;  c1.w = row_acc[7] + bb1.w;
            float* cp = C + (size_t)(m0 + tm + 2 * ip + h) * N + n0 + tn;
            *(float4*)(cp)     = c0;
            *(float4*)(cp + 4) = c1;
        }
    }
}

// ---------------- BN stats: deterministic hierarchical reduction -------------
__global__ __launch_bounds__(256)
void bn_stats(const float* __restrict__ X, int C,
              float* __restrict__ psum, float* __restrict__ psq)
{
    __shared__ float ss[8][33];
    __shared__ float sq[8][33];
    const int c_l = threadIdx.x & 31;
    const int r_l = threadIdx.x >> 5;
    const int c   = blockIdx.x * 32 + c_l;
    const int mb  = blockIdx.y * 1024;

    float s = 0.0f, q = 0.0f;
    for (int m = mb + r_l; m < mb + 1024; m += 8) {
        float v = X[(size_t)m * C + c];
        s += v;
        q += v * v;
    }
    ss[r_l][c_l] = s;
    sq[r_l][c_l] = q;
    __syncthreads();
    if (r_l == 0) {
        float ts = 0.0f, tq = 0.0f;
        #pragma unroll
        for (int r = 0; r < 8; r++) { ts += ss[r][c_l]; tq += sq[r][c_l]; }
        psum[blockIdx.y * C + c] = ts;
        psq [blockIdx.y * C + c] = tq;
    }
}

__global__ void bn_final(const float* __restrict__ psum, const float* __restrict__ psq,
                         const float* __restrict__ gamma, const float* __restrict__ beta,
                         float* __restrict__ scale, float* __restrict__ shift, int C)
{
    const int c = blockIdx.x * blockDim.x + threadIdx.x;
    if (c >= C) return;
    float s = 0.0f, q = 0.0f;
    #pragma unroll
    for (int i = 0; i < 8; i++) { s += psum[i * C + c]; q += psq[i * C + c]; }
    const float invM = 1.0f / (float)M_ROWS;
    float mean = s * invM;
    float var  = q * invM - mean * mean;
    float rstd = 1.0f / sqrtf(var + EPS_BN);
    float sc   = gamma[c] * rstd;
    scale[c] = sc;
    shift[c] = beta[c] - mean * sc;
}

// ---------------- fused BN-apply + dual adaptive LIF scan over T -------------
__global__ __launch_bounds__(256)
void bn_lif(const float* __restrict__ X, const float* __restrict__ scale,
            const float* __restrict__ shift, float* __restrict__ S, int C)
{
    const int idx = blockIdx.x * blockDim.x + threadIdx.x;   // over N_BATCH*C
    const int c = idx % C;
    const int n = idx / C;
    const float sc = scale[c];
    const float sh = shift[c];

    float v = 0.0f, a = 0.0f;
    #pragma unroll
    for (int t = 0; t < T_DIM; t++) {
        const size_t off = ((size_t)t * N_BATCH + n) * C + c;
        float u = fmaf(X[off], sc, sh);
        v = __fadd_rn(v, __fmul_rn(__fsub_rn(u, v), 0.5f));
        float th = __fadd_rn(1.0f, __fmul_rn(0.1f, a));
        float sp = (v >= th ? 1.0f : 0.0f) - (-v >= th ? 1.0f : 0.0f);
        v = __fsub_rn(v, __fmul_rn(sp, th));
        a = __fadd_rn(__fmul_rn(0.9f, a), fabsf(sp));
        S[off] = sp;
    }
}

// ---------------- launch ----------------
extern "C" void kernel_launch(void* const* d_in, const int* in_sizes, int n_in,
                              void* d_out, int out_size)
{
    const float* x   = (const float*)d_in[0];
    const float* W1  = (const float*)d_in[1];
    const float* b1  = (const float*)d_in[2];
    const float* g1  = (const float*)d_in[3];
    const float* be1 = (const float*)d_in[4];
    const float* W2  = (const float*)d_in[5];
    const float* b2  = (const float*)d_in[6];
    const float* g2  = (const float*)d_in[7];
    const float* be2 = (const float*)d_in[8];
    float* out = (float*)d_out;

    float *h, *s, *o, *psum, *psq, *scale, *shift;
    cudaGetSymbolAddress((void**)&h,     g_h);
    cudaGetSymbolAddress((void**)&s,     g_s);
    cudaGetSymbolAddress((void**)&o,     g_o);
    cudaGetSymbolAddress((void**)&psum,  g_psum);
    cudaGetSymbolAddress((void**)&psq,   g_psq);
    cudaGetSymbolAddress((void**)&scale, g_scale);
    cudaGetSymbolAddress((void**)&shift, g_shift);

    // ---- layer 1: fc1 -> bn1 -> lif1 ----
    sgemm_nt_bias<<<dim3(H_DIM / 128, M_ROWS / 128), 256>>>(x, W1, b1, h, H_DIM, D_DIM);
    bn_stats<<<dim3(H_DIM / 32, 8), 256>>>(h, H_DIM, psum, psq);
    bn_final<<<H_DIM / 256, 256>>>(psum, psq, g1, be1, scale, shift, H_DIM);
    bn_lif<<<(N_BATCH * H_DIM) / 256, 256>>>(h, scale, shift, s, H_DIM);

    // ---- layer 2: fc2 -> bn2 -> lif2 ----
    sgemm_nt_bias<<<dim3(D_DIM / 128, M_ROWS / 128), 256>>>(s, W2, b2, o, D_DIM, H_DIM);
    bn_stats<<<dim3(D_DIM / 32, 8), 256>>>(o, D_DIM, psum, psq);
    bn_final<<<D_DIM / 256, 256>>>(psum, psq, g2, be2, scale, shift, D_DIM);
    bn_lif<<<(N_BATCH * D_DIM) / 256, 256>>>(o, scale, shift, out, D_DIM);
}

// round 17
// speedup vs baseline: 2.2667x; 2.2667x over previous
#include <cuda_runtime.h>
#include <cuda_bf16.h>
#include <math.h>
#include <stdint.h>

// Problem dims (fixed)
#define T_DIM   32
#define N_BATCH 256
#define D_DIM   512
#define H_DIM   2048
#define M_ROWS  (T_DIM * N_BATCH)   // 8192
#define EPS_BN  1e-5f

// ---------------- scratch (device globals; no allocs allowed) ----------------
__device__ float g_h[(size_t)M_ROWS * H_DIM];   // fc1 pre-activation (64 MB)
__device__ float g_s[(size_t)M_ROWS * H_DIM];   // layer-1 spikes     (64 MB)
__device__ float g_o[(size_t)M_ROWS * D_DIM];   // fc2 pre-activation (16 MB)
__device__ float g_w2t[(size_t)H_DIM * D_DIM];  // W2 transposed [k][c] (4 MB)
__device__ int   g_lists[(size_t)M_ROWS * H_DIM];  // per-row (k<<1|neg), 64 MB
__device__ int   g_offs[M_ROWS * 9];               // per-row k-tile offsets
__device__ float g_psum[8 * H_DIM];
__device__ float g_psq [8 * H_DIM];
__device__ float g_scale[H_DIM];
__device__ float g_shift[H_DIM];

// ---------------- PROVEN round-2 scalar SGEMM (fc1) --------------------------
__global__ __launch_bounds__(256)
void sgemm_nt_bias(const float* __restrict__ A, const float* __restrict__ B,
                   const float* __restrict__ bias, float* __restrict__ C,
                   int N, int K)
{
    __shared__ float As[2][16][128];
    __shared__ float Bs[2][16][128];

    const int tid = threadIdx.x;
    const int m0  = blockIdx.y * 128;
    const int n0  = blockIdx.x * 128;
    const int tm  = (tid >> 4) * 8;
    const int tn  = (tid & 15) * 8;

    const int lrow = tid >> 2;
    const int lk4  = (tid & 3) * 4;

    const float* Aptr = A + (size_t)(m0 + lrow) * K + lk4;
    const float* Bptr = B + (size_t)(n0 + lrow) * K + lk4;
    const size_t rstep = (size_t)64 * K;

    float acc[8][8];
    #pragma unroll
    for (int i = 0; i < 8; i++)
        #pragma unroll
        for (int j = 0; j < 8; j++) acc[i][j] = 0.0f;

    float4 ar0, ar1, br0, br1;

    ar0 = *(const float4*)(Aptr);
    ar1 = *(const float4*)(Aptr + rstep);
    br0 = *(const float4*)(Bptr);
    br1 = *(const float4*)(Bptr + rstep);
    #pragma unroll
    for (int j = 0; j < 4; j++) {
        As[0][lk4 + j][lrow]      = ((const float*)&ar0)[j];
        As[0][lk4 + j][lrow + 64] = ((const float*)&ar1)[j];
        Bs[0][lk4 + j][lrow]      = ((const float*)&br0)[j];
        Bs[0][lk4 + j][lrow + 64] = ((const float*)&br1)[j];
    }
    __syncthreads();

    const int nk = K >> 4;
    for (int kt = 0; kt < nk; kt++) {
        const int b = kt & 1;
        if (kt + 1 < nk) {
            const float* Ap = Aptr + (size_t)(kt + 1) * 16;
            const float* Bp = Bptr + (size_t)(kt + 1) * 16;
            ar0 = *(const float4*)(Ap);
            ar1 = *(const float4*)(Ap + rstep);
            br0 = *(const float4*)(Bp);
            br1 = *(const float4*)(Bp + rstep);
        }
        #pragma unroll
        for (int k = 0; k < 16; k++) {
            float4 a0 = *(const float4*)&As[b][k][tm];
            float4 a1 = *(const float4*)&As[b][k][tm + 4];
            float4 b0 = *(const float4*)&Bs[b][k][tn];
            float4 b1 = *(const float4*)&Bs[b][k][tn + 4];
            float av[8] = {a0.x, a0.y, a0.z, a0.w, a1.x, a1.y, a1.z, a1.w};
            float bv[8] = {b0.x, b0.y, b0.z, b0.w, b1.x, b1.y, b1.z, b1.w};
            #pragma unroll
            for (int i = 0; i < 8; i++)
                #pragma unroll
                for (int j = 0; j < 8; j++)
                    acc[i][j] = fmaf(av[i], bv[j], acc[i][j]);
        }
        if (kt + 1 < nk) {
            const int nb = b ^ 1;
            #pragma unroll
            for (int j = 0; j < 4; j++) {
                As[nb][lk4 + j][lrow]      = ((const float*)&ar0)[j];
                As[nb][lk4 + j][lrow + 64] = ((const float*)&ar1)[j];
                Bs[nb][lk4 + j][lrow]      = ((const float*)&br0)[j];
                Bs[nb][lk4 + j][lrow + 64] = ((const float*)&br1)[j];
            }
            __syncthreads();
        }
    }

    const float4 bb0 = *(const float4*)(bias + n0 + tn);
    const float4 bb1 = *(const float4*)(bias + n0 + tn + 4);
    #pragma unroll
    for (int i = 0; i < 8; i++) {
        float4 c0, c1;
        c0.x = acc[i][0] + bb0.x;  c0.y = acc[i][1] + bb0.y;
        c0.z = acc[i][2] + bb0.z;  c0.w = acc[i][3] + bb0.w;
        c1.x = acc[i][4] + bb1.x;  c1.y = acc[i][5] + bb1.y;
        c1.z = acc[i][6] + bb1.z;  c1.w = acc[i][7] + bb1.w;
        float* cp = C + (size_t)(m0 + tm + i) * N + n0 + tn;
        *(float4*)(cp)     = c0;
        *(float4*)(cp + 4) = c1;
    }
}

// ---------------- BN stats (round-2 proven) ----------------------------------
__global__ __launch_bounds__(256)
void bn_stats(const float* __restrict__ X, int C,
              float* __restrict__ psum, float* __restrict__ psq)
{
    __shared__ float ss[8][33];
    __shared__ float sq[8][33];
    const int c_l = threadIdx.x & 31;
    const int r_l = threadIdx.x >> 5;
    const int c   = blockIdx.x * 32 + c_l;
    const int mb  = blockIdx.y * 1024;

    float s = 0.0f, q = 0.0f;
    for (int m = mb + r_l; m < mb + 1024; m += 8) {
        float v = X[(size_t)m * C + c];
        s += v;
        q += v * v;
    }
    ss[r_l][c_l] = s;
    sq[r_l][c_l] = q;
    __syncthreads();
    if (r_l == 0) {
        float ts = 0.0f, tq = 0.0f;
        #pragma unroll
        for (int r = 0; r < 8; r++) { ts += ss[r][c_l]; tq += sq[r][c_l]; }
        psum[blockIdx.y * C + c] = ts;
        psq [blockIdx.y * C + c] = tq;
    }
}

__global__ void bn_final(const float* __restrict__ psum, const float* __restrict__ psq,
                         const float* __restrict__ gamma, const float* __restrict__ beta,
                         float* __restrict__ scale, float* __restrict__ shift, int C)
{
    const int c = blockIdx.x * blockDim.x + threadIdx.x;
    if (c >= C) return;
    float s = 0.0f, q = 0.0f;
    #pragma unroll
    for (int i = 0; i < 8; i++) { s += psum[i * C + c]; q += psq[i * C + c]; }
    const float invM = 1.0f / (float)M_ROWS;
    float mean = s * invM;
    float var  = q * invM - mean * mean;
    float rstd = 1.0f / sqrtf(var + EPS_BN);
    float sc   = gamma[c] * rstd;
    scale[c] = sc;
    shift[c] = beta[c] - mean * sc;
}

// ---------------- fused BN-apply + LIF (round-2 proven) ----------------------
__global__ __launch_bounds__(256)
void bn_lif(const float* __restrict__ X, const float* __restrict__ scale,
            const float* __restrict__ shift, float* __restrict__ S, int C)
{
    const int idx = blockIdx.x * blockDim.x + threadIdx.x;
    const int c = idx % C;
    const int n = idx / C;
    const float sc = scale[c];
    const float sh = shift[c];

    float v = 0.0f, a = 0.0f;
    #pragma unroll
    for (int t = 0; t < T_DIM; t++) {
        const size_t off = ((size_t)t * N_BATCH + n) * C + c;
        float u = fmaf(X[off], sc, sh);
        v = __fadd_rn(v, __fmul_rn(__fsub_rn(u, v), 0.5f));
        float th = __fadd_rn(1.0f, __fmul_rn(0.1f, a));
        float sp = (v >= th ? 1.0f : 0.0f) - (-v >= th ? 1.0f : 0.0f);
        v = __fsub_rn(v, __fmul_rn(sp, th));
        a = __fadd_rn(__fmul_rn(0.9f, a), fabsf(sp));
        S[off] = sp;
    }
}

// ---------------- W2 transpose: [C=512][K=2048] -> [K][C] --------------------
__global__ __launch_bounds__(256)
void transpose_w2(const float* __restrict__ W2, float* __restrict__ W2T)
{
    __shared__ float tile[32][33];
    const int kb = blockIdx.x * 32;
    const int cb = blockIdx.y * 32;
    const int tx = threadIdx.x & 31;
    const int ty = threadIdx.x >> 5;          // 0..7
    #pragma unroll
    for (int i = ty; i < 32; i += 8)
        tile[i][tx] = W2[(size_t)(cb + i) * H_DIM + kb + tx];
    __syncthreads();
    #pragma unroll
    for (int i = ty; i < 32; i += 8)
        W2T[(size_t)(kb + i) * D_DIM + cb + tx] = tile[tx][i];
}

// ---------------- pack spikes: per row, sorted (k<<1|neg) + tile offsets -----
// warp per row; ballot compaction; k ascending (deterministic).
__global__ __launch_bounds__(256)
void pack_spikes(const float* __restrict__ S, int* __restrict__ lists,
                 int* __restrict__ offs)
{
    const int row  = blockIdx.x * 8 + (threadIdx.x >> 5);
    const int lane = threadIdx.x & 31;
    const float* src = S + (size_t)row * H_DIM;
    int* lst = lists + (size_t)row * H_DIM;

    int total = 0;
    for (int base = 0; base < H_DIM; base += 32) {
        if ((base & 255) == 0 && lane == 0) offs[row * 9 + (base >> 8)] = total;
        float v = src[base + lane];
        unsigned bal = __ballot_sync(0xFFFFFFFFu, v != 0.0f);
        if (v != 0.0f) {
            int pos = total + __popc(bal & ((1u << lane) - 1u));
            lst[pos] = ((base + lane) << 1) | (v < 0.0f ? 1 : 0);
        }
        total += __popc(bal);
    }
    if (lane == 0) offs[row * 9 + 8] = total;
}

// ---------------- sparse exact fc2: O[m,c] = b2[c] + sum_k s[m,k]*W2[c,k] ----
// Skipping zeros + FADD/FSUB in ascending k is BITWISE identical to the
// round-2 fmaf chain (fmaf(0,w,a)=a, fmaf(+-1,w,a)=rn(a+-w)).
// CTA: 32 rows x 512 c; 128 threads (float4 each); k-tiles of 256 for L1 reuse.
__global__ __launch_bounds__(128)
void fc2_sparse(const int* __restrict__ lists, const int* __restrict__ offs,
                const float* __restrict__ W2T, const float* __restrict__ b2,
                float* __restrict__ O)
{
    const int c4 = threadIdx.x * 4;
    const int r0 = blockIdx.x * 32;

    float4 acc[32];
    #pragma unroll
    for (int r = 0; r < 32; r++) acc[r] = make_float4(0.f, 0.f, 0.f, 0.f);

    for (int kt = 0; kt < 8; kt++) {
        #pragma unroll
        for (int r = 0; r < 32; r++) {
            const int m  = r0 + r;
            const int jb = offs[m * 9 + kt];
            const int je = offs[m * 9 + kt + 1];
            const int* lst = lists + (size_t)m * H_DIM;
            for (int j = jb; j < je; j++) {
                const int pk = lst[j];                  // warp-uniform broadcast
                const float4 w = *(const float4*)(W2T + ((size_t)(pk >> 1) << 9) + c4);
                if (pk & 1) {
                    acc[r].x -= w.x; acc[r].y -= w.y; acc[r].z -= w.z; acc[r].w -= w.w;
                } else {
                    acc[r].x += w.x; acc[r].y += w.y; acc[r].z += w.z; acc[r].w += w.w;
                }
            }
        }
    }

    const float4 bb = *(const float4*)(b2 + c4);
    #pragma unroll
    for (int r = 0; r < 32; r++) {
        float4 v;
        v.x = acc[r].x + bb.x;  v.y = acc[r].y + bb.y;
        v.z = acc[r].z + bb.z;  v.w = acc[r].w + bb.w;
        *(float4*)(O + (size_t)(r0 + r) * D_DIM + c4) = v;
    }
}

// ---------------- launch ----------------
extern "C" void kernel_launch(void* const* d_in, const int* in_sizes, int n_in,
                              void* d_out, int out_size)
{
    const float* x   = (const float*)d_in[0];
    const float* W1  = (const float*)d_in[1];
    const float* b1  = (const float*)d_in[2];
    const float* g1  = (const float*)d_in[3];
    const float* be1 = (const float*)d_in[4];
    const float* W2  = (const float*)d_in[5];
    const float* b2  = (const float*)d_in[6];
    const float* g2  = (const float*)d_in[7];
    const float* be2 = (const float*)d_in[8];
    float* out = (float*)d_out;

    float *h, *s, *o, *w2t, *psum, *psq, *scale, *shift;
    int *lists, *offs;
    cudaGetSymbolAddress((void**)&h,     g_h);
    cudaGetSymbolAddress((void**)&s,     g_s);
    cudaGetSymbolAddress((void**)&o,     g_o);
    cudaGetSymbolAddress((void**)&w2t,   g_w2t);
    cudaGetSymbolAddress((void**)&lists, g_lists);
    cudaGetSymbolAddress((void**)&offs,  g_offs);
    cudaGetSymbolAddress((void**)&psum,  g_psum);
    cudaGetSymbolAddress((void**)&psq,   g_psq);
    cudaGetSymbolAddress((void**)&scale, g_scale);
    cudaGetSymbolAddress((void**)&shift, g_shift);

    // W2 transpose (independent of layer 1; issue first)
    transpose_w2<<<dim3(H_DIM / 32, D_DIM / 32), 256>>>(W2, w2t);

    // ---- layer 1: fc1 -> bn1 -> lif1 (all round-2 proven, exact) ----
    sgemm_nt_bias<<<dim3(H_DIM / 128, M_ROWS / 128), 256>>>(x, W1, b1, h, H_DIM, D_DIM);
    bn_stats<<<dim3(H_DIM / 32, 8), 256>>>(h, H_DIM, psum, psq);
    bn_final<<<H_DIM / 256, 256>>>(psum, psq, g1, be1, scale, shift, H_DIM);
    bn_lif<<<(N_BATCH * H_DIM) / 256, 256>>>(h, scale, shift, s, H_DIM);

    // ---- layer 2: pack ternary spikes -> sparse exact fc2 -> bn2 -> lif2 ----
    pack_spikes<<<M_ROWS / 8, 256>>>(s, lists, offs);
    fc2_sparse<<<M_ROWS / 32, 128>>>(lists, offs, w2t, b2, o);
    bn_stats<<<dim3(D_DIM / 32, 8), 256>>>(o, D_DIM, psum, psq);
    bn_final<<<D_DIM / 256, 256>>>(psum, psq, g2, be2, scale, shift, D_DIM);
    bn_lif<<<(N_BATCH * D_DIM) / 256, 256>>>(o, scale, shift, out, D_DIM);
}